// round 5
// baseline (speedup 1.0000x reference)
#include <cuda_runtime.h>
#include <cuda_bf16.h>
#include <math.h>

// Fixed problem shape (from reference): B=128, S=2048, E=512, H=512.
#define MAX_B 128
#define MAX_S 2048
#define MAX_E 512
#define MAX_H 512
#define SPLITK 4

__device__ float g_c[MAX_B];                        // c[b] = q[b].bk
__device__ float g_sum[MAX_B];                      // row sums of exp
__device__ unsigned g_cnt[MAX_B];                   // per-batch completion count
__device__ float g_part[SPLITK * MAX_B * MAX_H];    // q split-K partials
__device__ float g_part2[SPLITK * MAX_B * MAX_E];   // v split-K partials

// ---------------------------------------------------------------------------
// Split-K register-tiled GEMM. Block tile 32(M) x 64(N), thread tile 2x4,
// 256 threads, k-tile 32, grid (N/64, M/32, SPLITK).
// TRANSB=1: C = A @ Bm^T  (Bm [N,K] row-major). Block (0,0,0) also zeroes
//           the per-batch accumulators (runs before gemm2/score in stream).
// TRANSB=0/APART=1: A is a SPLITK-partial array; partials summed + abias
//           added during A load. Blocks with blockIdx.x==0 also accumulate
//           c[m] = sum_k q[m,k]*cw[k] into g_c via atomicAdd.
// ---------------------------------------------------------------------------
template <int TRANSB, int APART>
__global__ __launch_bounds__(256) void gemm_split_kernel(
    const float* __restrict__ A, const float* __restrict__ abias,
    const float* __restrict__ Bm, const float* __restrict__ cw,
    float* __restrict__ Cpart, int M, int N, int K)
{
    __shared__ float As[32][33];
    __shared__ float Bs[32][65];
    int tid = threadIdx.x;
    int m0 = blockIdx.y * 32;
    int n0 = blockIdx.x * 64;
    int kidx = blockIdx.z;
    int kbeg = kidx * (K / SPLITK);
    int kend = kbeg + (K / SPLITK);

    if (TRANSB) {  // gemm1: zero per-batch accumulators once
        if (blockIdx.x == 0 && blockIdx.y == 0 && blockIdx.z == 0 && tid < MAX_B) {
            g_c[tid] = 0.0f;
            g_sum[tid] = 0.0f;
            g_cnt[tid] = 0u;
        }
    }

    int tx = tid & 15;
    int ty = tid >> 4;
    float acc[2][4] = {};
    float cpart = 0.0f;

    for (int k0 = kbeg; k0 < kend; k0 += 32) {
        {
            int r = tid >> 3;
            int kq = (tid & 7) * 4;
            size_t off = (size_t)(m0 + r) * K + k0 + kq;
            float4 a;
            if (APART) {
                int MK = M * K;
                float4 p0 = *(const float4*)&A[off];
                float4 p1 = *(const float4*)&A[MK + off];
                float4 p2 = *(const float4*)&A[2 * MK + off];
                float4 p3 = *(const float4*)&A[3 * MK + off];
                float4 bb = *(const float4*)&abias[k0 + kq];
                a.x = p0.x + p1.x + p2.x + p3.x + bb.x;
                a.y = p0.y + p1.y + p2.y + p3.y + bb.y;
                a.z = p0.z + p1.z + p2.z + p3.z + bb.z;
                a.w = p0.w + p1.w + p2.w + p3.w + bb.w;
            } else {
                a = *(const float4*)&A[off];
            }
            As[r][kq] = a.x; As[r][kq + 1] = a.y; As[r][kq + 2] = a.z; As[r][kq + 3] = a.w;
        }
        if (TRANSB) {
#pragma unroll
            for (int t = 0; t < 2; t++) {
                int idx = tid + t * 256;
                int n = idx >> 3;
                int kq = (idx & 7) * 4;
                float4 v = *(const float4*)&Bm[(size_t)(n0 + n) * K + k0 + kq];
                Bs[kq][n] = v.x; Bs[kq + 1][n] = v.y; Bs[kq + 2][n] = v.z; Bs[kq + 3][n] = v.w;
            }
        } else {
#pragma unroll
            for (int t = 0; t < 2; t++) {
                int idx = tid + t * 256;
                int kk = idx >> 4;
                int nq = (idx & 15) * 4;
                float4 v = *(const float4*)&Bm[(size_t)(k0 + kk) * N + n0 + nq];
                Bs[kk][nq] = v.x; Bs[kk][nq + 1] = v.y; Bs[kk][nq + 2] = v.z; Bs[kk][nq + 3] = v.w;
            }
        }
        __syncthreads();
#pragma unroll
        for (int kk = 0; kk < 32; kk++) {
            float a0 = As[ty * 2][kk];
            float a1 = As[ty * 2 + 1][kk];
            float b0 = Bs[kk][tx * 4];
            float b1 = Bs[kk][tx * 4 + 1];
            float b2 = Bs[kk][tx * 4 + 2];
            float b3 = Bs[kk][tx * 4 + 3];
            acc[0][0] += a0 * b0; acc[0][1] += a0 * b1; acc[0][2] += a0 * b2; acc[0][3] += a0 * b3;
            acc[1][0] += a1 * b0; acc[1][1] += a1 * b1; acc[1][2] += a1 * b2; acc[1][3] += a1 * b3;
        }
        if (APART && blockIdx.x == 0 && tid < 32) {
            // c partial for row m0+tid over this k-tile (As holds summed q + bias)
#pragma unroll
            for (int kk = 0; kk < 32; kk++)
                cpart += As[tid][kk] * __ldg(&cw[k0 + kk]);
        }
        __syncthreads();
    }
#pragma unroll
    for (int r = 0; r < 2; r++)
#pragma unroll
        for (int c = 0; c < 4; c++)
            Cpart[(size_t)kidx * M * N + (size_t)(m0 + ty * 2 + r) * N + n0 + tx * 4 + c] = acc[r][c];

    if (APART && blockIdx.x == 0 && tid < 32)
        atomicAdd(&g_c[m0 + tid], cpart);
}

// ---------------------------------------------------------------------------
// Score + softmax with masked-row skipping and block-level load balancing.
// Rows of the 256-row block whose mask==1 get 0 (their target data is never
// read). Kept rows are compacted into s_list; warps take rows round-robin
// (position = warp + 8*t), so per-warp counts differ by <=1.
// Last block per batch b normalizes its row. E fixed at 512.
// grid (S/256, B), 256 threads (8 warps).
// ---------------------------------------------------------------------------
__global__ __launch_bounds__(256, 4) void score_kernel(
    const float* __restrict__ target, const int* __restrict__ mask,
    float* __restrict__ out, int S)
{
    __shared__ float4 vsh[128];
    __shared__ unsigned char s_list[256];
    __shared__ int s_wcnt[8];
    __shared__ int s_wbase[9];
    __shared__ bool lastdone;
    int b = blockIdx.y;
    int tid = threadIdx.x;
    int warp = tid >> 5;
    int lane = tid & 31;
    int sblk = blockIdx.x * 256;

    // v[b] reduced from split-K partials into smem
    {
        const int BE4 = MAX_B * MAX_E / 4;
        const float4* vp = reinterpret_cast<const float4*>(&g_part2[0]) + b * 128;
        if (tid < 128) {
            float4 p0 = vp[tid];
            float4 p1 = vp[BE4 + tid];
            float4 p2 = vp[2 * BE4 + tid];
            float4 p3 = vp[3 * BE4 + tid];
            float4 r;
            r.x = p0.x + p1.x + p2.x + p3.x;
            r.y = p0.y + p1.y + p2.y + p3.y;
            r.z = p0.z + p1.z + p2.z + p3.z;
            r.w = p0.w + p1.w + p2.w + p3.w;
            vsh[tid] = r;
        }
    }

    const int* mrow = mask + (size_t)b * S;
    float* erow = out + (size_t)b * S;
    const float4* tb = reinterpret_cast<const float4*>(target) +
                       ((size_t)b * S + sblk) * 128;

    // compact kept rows (thread tid owns row tid of this block)
    bool keep = (mrow[sblk + tid] != 1);
    if (!keep) erow[sblk + tid] = 0.0f;
    unsigned bits = __ballot_sync(0xffffffffu, keep);
    if (lane == 0) s_wcnt[warp] = __popc(bits);
    __syncthreads();
    if (tid == 0) {
        int a = 0;
#pragma unroll
        for (int w = 0; w < 8; w++) { s_wbase[w] = a; a += s_wcnt[w]; }
        s_wbase[8] = a;
    }
    __syncthreads();
    if (keep)
        s_list[s_wbase[warp] + __popc(bits & ((1u << lane) - 1))] = (unsigned char)tid;
    __syncthreads();
    int nk = s_wbase[8];

    float cb = g_c[b];
    float esum = 0.0f;

#define LOADROW(buf, r) { const float4* t_ = tb + (size_t)(r) * 128;            \
        buf[0] = __ldcs(t_ + lane);       buf[1] = __ldcs(t_ + lane + 32);      \
        buf[2] = __ldcs(t_ + lane + 64);  buf[3] = __ldcs(t_ + lane + 96); }

#define DOTV(buf, a) { a = 0.0f;                                                \
        _Pragma("unroll") for (int j_ = 0; j_ < 4; j_++) {                      \
            float4 x_ = buf[j_]; float4 v_ = vsh[lane + 32 * j_];               \
            a += x_.x * v_.x + x_.y * v_.y + x_.z * v_.z + x_.w * v_.w; } }

#define REDUCE_EMIT(a, r) {                                                     \
        _Pragma("unroll") for (int o_ = 16; o_; o_ >>= 1)                       \
            a += __shfl_xor_sync(0xffffffffu, a, o_);                           \
        if (lane == 0) {                                                        \
            float e_ = expf(10.0f * tanhf(a + cb) - 10.0f);                     \
            erow[sblk + (r)] = e_; esum += e_; } }

    {
        float4 bufA[4], bufB[4];
        int rA = (warp < nk) ? (int)s_list[warp] : -1;
        int rB = (warp + 8 < nk) ? (int)s_list[warp + 8] : -1;
        if (rA >= 0) LOADROW(bufA, rA);
        if (rB >= 0) LOADROW(bufB, rB);
        int pn = warp + 16;
        while (rA >= 0) {
            float a;
            DOTV(bufA, a);
            int rn = (pn < nk) ? (int)s_list[pn] : -1; pn += 8;
            if (rn >= 0) LOADROW(bufA, rn);
            REDUCE_EMIT(a, rA);
            rA = rn;
            if (rB < 0) break;
            rn = (pn < nk) ? (int)s_list[pn] : -1; pn += 8;
            DOTV(bufB, a);
            if (rn >= 0) LOADROW(bufB, rn);
            REDUCE_EMIT(a, rB);
            rB = rn;
        }
    }

    if (lane == 0 && esum != 0.0f)
        atomicAdd(&g_sum[b], esum);

    __threadfence();
    __syncthreads();
    if (tid == 0) {
        unsigned t = atomicAdd(&g_cnt[b], 1u);
        lastdone = (t == gridDim.x - 1);
    }
    __syncthreads();

    if (lastdone) {
        __threadfence();
        float inv = 1.0f / g_sum[b];
        float4* rowv = reinterpret_cast<float4*>(out + (size_t)b * S);
        for (int i = tid; i < S / 4; i += 256) {
            float4 x = rowv[i];
            x.x *= inv; x.y *= inv; x.z *= inv; x.w *= inv;
            rowv[i] = x;
        }
    }
}

// ---------------------------------------------------------------------------
// Inputs (metadata order): query[B,E], target[B,S,E], mask[B,S],
//                          Wq[H,E], bq[H], Wk[H,E], bk[H]
// Output: alpha[B,S] float32
// ---------------------------------------------------------------------------
extern "C" void kernel_launch(void* const* d_in, const int* in_sizes, int n_in,
                              void* d_out, int out_size)
{
    const float* query  = (const float*)d_in[0];
    const float* target = (const float*)d_in[1];
    const int*   mask   = (const int*)d_in[2];
    const float* Wq     = (const float*)d_in[3];
    const float* bq     = (const float*)d_in[4];
    const float* Wk     = (const float*)d_in[5];
    const float* bk     = (const float*)d_in[6];
    float* out = (float*)d_out;

    int H = in_sizes[4];
    int E = in_sizes[1] / in_sizes[2];
    int B = in_sizes[0] / E;
    int S = in_sizes[2] / B;

    float* part_ptr; float* part2_ptr;
    cudaGetSymbolAddress((void**)&part_ptr, g_part);
    cudaGetSymbolAddress((void**)&part2_ptr, g_part2);

    // q partials: query @ Wq^T -> g_part  (also zeroes g_c/g_sum/g_cnt)
    {
        dim3 grid(H / 64, B / 32, SPLITK);
        gemm_split_kernel<1, 0><<<grid, 256>>>(query, nullptr, Wq, nullptr,
                                               part_ptr, B, H, E);
    }
    // v partials: (q summed + bq) @ Wk -> g_part2 ; also accumulates c[b]
    {
        dim3 grid(E / 64, B / 32, SPLITK);
        gemm_split_kernel<0, 1><<<grid, 256>>>(part_ptr, bq, Wk, bk,
                                               part2_ptr, B, E, H);
    }
    // fused score + softmax (mask-skip, balanced, last-block normalize)
    {
        dim3 grid(S / 256, B);
        score_kernel<<<grid, 256>>>(target, mask, out, S);
    }
}

// round 6
// speedup vs baseline: 1.0574x; 1.0574x over previous
#include <cuda_runtime.h>
#include <cuda_bf16.h>
#include <math.h>

// Fixed problem shape (from reference): B=128, S=2048, E=512, H=512.
#define MAX_B 128
#define MAX_S 2048
#define MAX_E 512
#define MAX_H 512
#define SPLITK 8

__device__ float g_c[MAX_B];                        // c[b] = q[b].bk
__device__ float g_sum[MAX_B];                      // row sums of exp
__device__ unsigned g_cnt[MAX_B];                   // per-batch completion count
__device__ float g_part[SPLITK * MAX_B * MAX_H];    // q split-K partials
__device__ float g_part2[SPLITK * MAX_B * MAX_E];   // v split-K partials

// ---------------------------------------------------------------------------
// Single-round split-K GEMM. Block tile 32(M) x 64(N), k-chunk = K/SPLITK = 64
// loaded in ONE round (no k-loop): all loads issued, one sync, 512 FMA/thread.
// grid (N/64, M/32, SPLITK), 256 threads, thread tile 2x4.
// TRANSB=1: C = A @ Bm^T  (Bm [N,K] row-major). Block (0,0,0) zeroes the
//           per-batch accumulators (stream-ordered before gemm2/score).
// TRANSB=0/APART=1: A is a SPLITK-partial array; the 8 partials are summed
//           (+abias) during the A load. blockIdx.x==0 blocks also accumulate
//           c[m] += sum_k q[m,k]*cw[k] into g_c via atomicAdd.
// ---------------------------------------------------------------------------
template <int TRANSB, int APART>
__global__ __launch_bounds__(256) void gemm_split_kernel(
    const float* __restrict__ A, const float* __restrict__ abias,
    const float* __restrict__ Bm, const float* __restrict__ cw,
    float* __restrict__ Cpart, int M, int N, int K)
{
    __shared__ float As[32][65];   // scalar access, conflict-free
    __shared__ float Bs[64][68];   // 16B-aligned rows -> LDS.128
    int tid = threadIdx.x;
    int m0 = blockIdx.y * 32;
    int n0 = blockIdx.x * 64;
    int kbeg = blockIdx.z * 64;

    if (TRANSB) {  // gemm1: zero per-batch accumulators once
        if (blockIdx.x == 0 && blockIdx.y == 0 && blockIdx.z == 0 && tid < MAX_B) {
            g_c[tid] = 0.0f;
            g_sum[tid] = 0.0f;
            g_cnt[tid] = 0u;
        }
    }

    // ---- A strip: 32 x 64 = 512 float4, 2 per thread ----
#pragma unroll
    for (int t = 0; t < 2; t++) {
        int idx = tid + t * 256;
        int r = idx >> 4;            // 0..31
        int kq = (idx & 15) * 4;     // 0..60
        size_t off = (size_t)(m0 + r) * K + kbeg + kq;
        float4 a;
        if (APART) {
            int MK = M * K;
            float4 s = *(const float4*)&abias[kbeg + kq];
#pragma unroll
            for (int p = 0; p < SPLITK; p++) {
                float4 pp = *(const float4*)&A[(size_t)p * MK + off];
                s.x += pp.x; s.y += pp.y; s.z += pp.z; s.w += pp.w;
            }
            a = s;
        } else {
            a = *(const float4*)&A[off];
        }
        As[r][kq] = a.x; As[r][kq + 1] = a.y; As[r][kq + 2] = a.z; As[r][kq + 3] = a.w;
    }

    // ---- B strip: 64n x 64k = 1024 float4, 4 per thread ----
    if (TRANSB) {
#pragma unroll
        for (int t = 0; t < 4; t++) {
            int idx = tid + t * 256;
            int n = idx >> 4;            // 0..63
            int kq = (idx & 15) * 4;     // 0..60
            float4 v = *(const float4*)&Bm[(size_t)(n0 + n) * K + kbeg + kq];
            Bs[kq][n] = v.x; Bs[kq + 1][n] = v.y; Bs[kq + 2][n] = v.z; Bs[kq + 3][n] = v.w;
        }
    } else {
#pragma unroll
        for (int t = 0; t < 4; t++) {
            int idx = tid + t * 256;
            int kk = idx >> 4;           // 0..63
            int nq = (idx & 15) * 4;     // 0..60
            *(float4*)&Bs[kk][nq] = *(const float4*)&Bm[(size_t)(kbeg + kk) * N + n0 + nq];
        }
    }
    __syncthreads();

    int tx = tid & 15;
    int ty = tid >> 4;
    float acc[2][4] = {};
#pragma unroll
    for (int kk = 0; kk < 64; kk++) {
        float a0 = As[ty * 2][kk];
        float a1 = As[ty * 2 + 1][kk];
        float4 bv = *(const float4*)&Bs[kk][tx * 4];
        acc[0][0] += a0 * bv.x; acc[0][1] += a0 * bv.y; acc[0][2] += a0 * bv.z; acc[0][3] += a0 * bv.w;
        acc[1][0] += a1 * bv.x; acc[1][1] += a1 * bv.y; acc[1][2] += a1 * bv.z; acc[1][3] += a1 * bv.w;
    }

#pragma unroll
    for (int r = 0; r < 2; r++) {
        float4 o = make_float4(acc[r][0], acc[r][1], acc[r][2], acc[r][3]);
        *(float4*)&Cpart[(size_t)blockIdx.z * M * N +
                         (size_t)(m0 + ty * 2 + r) * N + n0 + tx * 4] = o;
    }

    if (APART && blockIdx.x == 0 && tid < 32) {
        float cpart = 0.0f;
#pragma unroll
        for (int kk = 0; kk < 64; kk++)
            cpart += As[tid][kk] * __ldg(&cw[kbeg + kk]);
        atomicAdd(&g_c[m0 + tid], cpart);
    }
}

// ---------------------------------------------------------------------------
// Score + softmax with masked-row skipping and block-level load balancing.
// Rows with mask==1 get 0 and their target data is never read. Kept rows are
// compacted into s_list; warps take rows round-robin so counts differ by <=1.
// Last block per batch b normalizes its row. E fixed at 512.
// grid (S/256, B), 256 threads (8 warps).
// ---------------------------------------------------------------------------
__global__ __launch_bounds__(256, 4) void score_kernel(
    const float* __restrict__ target, const int* __restrict__ mask,
    float* __restrict__ out, int S)
{
    __shared__ float4 vsh[128];
    __shared__ unsigned char s_list[256];
    __shared__ int s_wcnt[8];
    __shared__ int s_wbase[9];
    __shared__ bool lastdone;
    int b = blockIdx.y;
    int tid = threadIdx.x;
    int warp = tid >> 5;
    int lane = tid & 31;
    int sblk = blockIdx.x * 256;

    // v[b] reduced from 8 split-K partials into smem
    {
        const int BE4 = MAX_B * MAX_E / 4;
        const float4* vp = reinterpret_cast<const float4*>(&g_part2[0]) + b * 128;
        if (tid < 128) {
            float4 r = vp[tid];
#pragma unroll
            for (int p = 1; p < SPLITK; p++) {
                float4 pp = vp[p * BE4 + tid];
                r.x += pp.x; r.y += pp.y; r.z += pp.z; r.w += pp.w;
            }
            vsh[tid] = r;
        }
    }

    const int* mrow = mask + (size_t)b * S;
    float* erow = out + (size_t)b * S;
    const float4* tb = reinterpret_cast<const float4*>(target) +
                       ((size_t)b * S + sblk) * 128;

    // compact kept rows (thread tid owns row tid of this block)
    bool keep = (mrow[sblk + tid] != 1);
    if (!keep) erow[sblk + tid] = 0.0f;
    unsigned bits = __ballot_sync(0xffffffffu, keep);
    if (lane == 0) s_wcnt[warp] = __popc(bits);
    __syncthreads();
    if (tid == 0) {
        int a = 0;
#pragma unroll
        for (int w = 0; w < 8; w++) { s_wbase[w] = a; a += s_wcnt[w]; }
        s_wbase[8] = a;
    }
    __syncthreads();
    if (keep)
        s_list[s_wbase[warp] + __popc(bits & ((1u << lane) - 1))] = (unsigned char)tid;
    __syncthreads();
    int nk = s_wbase[8];

    float cb = g_c[b];
    float esum = 0.0f;

#define LOADROW(buf, r) { const float4* t_ = tb + (size_t)(r) * 128;            \
        buf[0] = __ldcs(t_ + lane);       buf[1] = __ldcs(t_ + lane + 32);      \
        buf[2] = __ldcs(t_ + lane + 64);  buf[3] = __ldcs(t_ + lane + 96); }

#define DOTV(buf, a) { a = 0.0f;                                                \
        _Pragma("unroll") for (int j_ = 0; j_ < 4; j_++) {                      \
            float4 x_ = buf[j_]; float4 v_ = vsh[lane + 32 * j_];               \
            a += x_.x * v_.x + x_.y * v_.y + x_.z * v_.z + x_.w * v_.w; } }

#define REDUCE_EMIT(a, r) {                                                     \
        _Pragma("unroll") for (int o_ = 16; o_; o_ >>= 1)                       \
            a += __shfl_xor_sync(0xffffffffu, a, o_);                           \
        if (lane == 0) {                                                        \
            float e_ = expf(10.0f * tanhf(a + cb) - 10.0f);                     \
            erow[sblk + (r)] = e_; esum += e_; } }

    {
        float4 bufA[4], bufB[4];
        int rA = (warp < nk) ? (int)s_list[warp] : -1;
        int rB = (warp + 8 < nk) ? (int)s_list[warp + 8] : -1;
        if (rA >= 0) LOADROW(bufA, rA);
        if (rB >= 0) LOADROW(bufB, rB);
        int pn = warp + 16;
        while (rA >= 0) {
            float a;
            DOTV(bufA, a);
            int rn = (pn < nk) ? (int)s_list[pn] : -1; pn += 8;
            if (rn >= 0) LOADROW(bufA, rn);
            REDUCE_EMIT(a, rA);
            rA = rn;
            if (rB < 0) break;
            rn = (pn < nk) ? (int)s_list[pn] : -1; pn += 8;
            DOTV(bufB, a);
            if (rn >= 0) LOADROW(bufB, rn);
            REDUCE_EMIT(a, rB);
            rB = rn;
        }
    }

    if (lane == 0 && esum != 0.0f)
        atomicAdd(&g_sum[b], esum);

    __threadfence();
    __syncthreads();
    if (tid == 0) {
        unsigned t = atomicAdd(&g_cnt[b], 1u);
        lastdone = (t == gridDim.x - 1);
    }
    __syncthreads();

    if (lastdone) {
        __threadfence();
        float inv = 1.0f / g_sum[b];
        float4* rowv = reinterpret_cast<float4*>(out + (size_t)b * S);
        for (int i = tid; i < S / 4; i += 256) {
            float4 x = rowv[i];
            x.x *= inv; x.y *= inv; x.z *= inv; x.w *= inv;
            rowv[i] = x;
        }
    }
}

// ---------------------------------------------------------------------------
// Inputs (metadata order): query[B,E], target[B,S,E], mask[B,S],
//                          Wq[H,E], bq[H], Wk[H,E], bk[H]
// Output: alpha[B,S] float32
// ---------------------------------------------------------------------------
extern "C" void kernel_launch(void* const* d_in, const int* in_sizes, int n_in,
                              void* d_out, int out_size)
{
    const float* query  = (const float*)d_in[0];
    const float* target = (const float*)d_in[1];
    const int*   mask   = (const int*)d_in[2];
    const float* Wq     = (const float*)d_in[3];
    const float* bq     = (const float*)d_in[4];
    const float* Wk     = (const float*)d_in[5];
    const float* bk     = (const float*)d_in[6];
    float* out = (float*)d_out;

    int H = in_sizes[4];
    int E = in_sizes[1] / in_sizes[2];
    int B = in_sizes[0] / E;
    int S = in_sizes[2] / B;

    float* part_ptr; float* part2_ptr;
    cudaGetSymbolAddress((void**)&part_ptr, g_part);
    cudaGetSymbolAddress((void**)&part2_ptr, g_part2);

    // q partials: query @ Wq^T -> g_part  (also zeroes g_c/g_sum/g_cnt)
    {
        dim3 grid(H / 64, B / 32, SPLITK);
        gemm_split_kernel<1, 0><<<grid, 256>>>(query, nullptr, Wq, nullptr,
                                               part_ptr, B, H, E);
    }
    // v partials: (q summed + bq) @ Wk -> g_part2 ; also accumulates c[b]
    {
        dim3 grid(E / 64, B / 32, SPLITK);
        gemm_split_kernel<0, 1><<<grid, 256>>>(part_ptr, bq, Wk, bk,
                                               part2_ptr, B, E, H);
    }
    // fused score + softmax (mask-skip, balanced, last-block normalize)
    {
        dim3 grid(S / 256, B);
        score_kernel<<<grid, 256>>>(target, mask, out, S);
    }
}

// round 7
// speedup vs baseline: 1.1317x; 1.0702x over previous
#include <cuda_runtime.h>
#include <cuda_bf16.h>
#include <math.h>

// Fixed problem shape (from reference): B=128, S=2048, E=512, H=512.
#define MAX_B 128
#define MAX_S 2048
#define MAX_E 512
#define MAX_H 512
#define SPLITK 8

__device__ float g_c[MAX_B];                        // c[b] = q[b].bk
__device__ float g_sum[MAX_B];                      // row sums of exp
__device__ unsigned g_cnt[MAX_B];                   // per-batch completion count
__device__ float g_part[SPLITK * MAX_B * MAX_H];    // q split-K partials
__device__ float g_part2[SPLITK * MAX_B * MAX_E];   // v split-K partials

// ---------------------------------------------------------------------------
// Single-round single-wave split-K GEMM. Block tile 64(M) x 64(N), k-chunk
// = K/SPLITK = 64 loaded in ONE round; grid (N/64, M/64, SPLITK) = 128 blocks
// = one wave. 256 threads, thread tile 4x4 -> 1024 FMA/thread.
// TRANSB=1: C = A @ Bm^T  (Bm [N,K] row-major). Block (0,0,0) zeroes the
//           per-batch accumulators (stream-ordered before gemm2/score).
// TRANSB=0/APART=1: A is a SPLITK-partial array; the 8 partials are summed
//           (+abias) during the A load. blockIdx.x==0 blocks also accumulate
//           c[m] += sum_k q[m,k]*cw[k] into g_c via atomicAdd (tid<64).
// ---------------------------------------------------------------------------
template <int TRANSB, int APART>
__global__ __launch_bounds__(256) void gemm_split_kernel(
    const float* __restrict__ A, const float* __restrict__ abias,
    const float* __restrict__ Bm, const float* __restrict__ cw,
    float* __restrict__ Cpart, int M, int N, int K)
{
    __shared__ float As[64][68];   // 68: float4-aligned, conflict-free
    __shared__ float Bs[64][68];
    int tid = threadIdx.x;
    int m0 = blockIdx.y * 64;
    int n0 = blockIdx.x * 64;
    int kbeg = blockIdx.z * 64;

    if (TRANSB) {  // gemm1: zero per-batch accumulators once
        if (blockIdx.x == 0 && blockIdx.y == 0 && blockIdx.z == 0 && tid < MAX_B) {
            g_c[tid] = 0.0f;
            g_sum[tid] = 0.0f;
            g_cnt[tid] = 0u;
        }
    }

    // ---- A strip: 64 x 64 = 1024 float4, 4 per thread ----
#pragma unroll
    for (int t = 0; t < 4; t++) {
        int idx = tid + t * 256;
        int r = idx >> 4;            // 0..63
        int kq = (idx & 15) * 4;     // 0..60
        size_t off = (size_t)(m0 + r) * K + kbeg + kq;
        float4 a;
        if (APART) {
            int MK = M * K;
            float4 s = *(const float4*)&abias[kbeg + kq];
#pragma unroll
            for (int p = 0; p < SPLITK; p++) {
                float4 pp = *(const float4*)&A[(size_t)p * MK + off];
                s.x += pp.x; s.y += pp.y; s.z += pp.z; s.w += pp.w;
            }
            a = s;
        } else {
            a = *(const float4*)&A[off];
        }
        *(float4*)&As[r][kq] = a;
    }

    // ---- B strip: 64 x 64 = 1024 float4, 4 per thread ----
    if (TRANSB) {
#pragma unroll
        for (int t = 0; t < 4; t++) {
            int idx = tid + t * 256;
            int n = idx >> 4;            // 0..63
            int kq = (idx & 15) * 4;     // 0..60
            float4 v = *(const float4*)&Bm[(size_t)(n0 + n) * K + kbeg + kq];
            Bs[kq][n] = v.x; Bs[kq + 1][n] = v.y; Bs[kq + 2][n] = v.z; Bs[kq + 3][n] = v.w;
        }
    } else {
#pragma unroll
        for (int t = 0; t < 4; t++) {
            int idx = tid + t * 256;
            int kk = idx >> 4;           // 0..63
            int nq = (idx & 15) * 4;     // 0..60
            *(float4*)&Bs[kk][nq] = *(const float4*)&Bm[(size_t)(kbeg + kk) * N + n0 + nq];
        }
    }
    __syncthreads();

    int tx = tid & 15;            // N groups of 4
    int ty = tid >> 4;            // M groups of 4 (0..15)
    float acc[4][4] = {};
#pragma unroll
    for (int kk = 0; kk < 64; kk++) {
        float a0 = As[ty * 4][kk];
        float a1 = As[ty * 4 + 1][kk];
        float a2 = As[ty * 4 + 2][kk];
        float a3 = As[ty * 4 + 3][kk];
        float4 bv = *(const float4*)&Bs[kk][tx * 4];
        acc[0][0] += a0 * bv.x; acc[0][1] += a0 * bv.y; acc[0][2] += a0 * bv.z; acc[0][3] += a0 * bv.w;
        acc[1][0] += a1 * bv.x; acc[1][1] += a1 * bv.y; acc[1][2] += a1 * bv.z; acc[1][3] += a1 * bv.w;
        acc[2][0] += a2 * bv.x; acc[2][1] += a2 * bv.y; acc[2][2] += a2 * bv.z; acc[2][3] += a2 * bv.w;
        acc[3][0] += a3 * bv.x; acc[3][1] += a3 * bv.y; acc[3][2] += a3 * bv.z; acc[3][3] += a3 * bv.w;
    }

#pragma unroll
    for (int r = 0; r < 4; r++) {
        float4 o = make_float4(acc[r][0], acc[r][1], acc[r][2], acc[r][3]);
        *(float4*)&Cpart[(size_t)blockIdx.z * M * N +
                         (size_t)(m0 + ty * 4 + r) * N + n0 + tx * 4] = o;
    }

    if (APART && blockIdx.x == 0 && tid < 64) {
        float cpart = 0.0f;
#pragma unroll
        for (int kk = 0; kk < 64; kk++)
            cpart += As[tid][kk] * __ldg(&cw[kbeg + kk]);
        atomicAdd(&g_c[m0 + tid], cpart);
    }
}

// ---------------------------------------------------------------------------
// Score + softmax with masked-row skipping and block-level load balancing.
// Rows with mask==1 get 0 and their target data is never read. Kept rows are
// compacted into s_list; warps take rows round-robin so counts differ by <=1.
// Last block per batch b normalizes its row. E fixed at 512.
// grid (S/256, B), 256 threads (8 warps).
// ---------------------------------------------------------------------------
__global__ __launch_bounds__(256, 4) void score_kernel(
    const float* __restrict__ target, const int* __restrict__ mask,
    float* __restrict__ out, int S)
{
    __shared__ float4 vsh[128];
    __shared__ unsigned char s_list[256];
    __shared__ int s_wcnt[8];
    __shared__ int s_wbase[9];
    __shared__ bool lastdone;
    int b = blockIdx.y;
    int tid = threadIdx.x;
    int warp = tid >> 5;
    int lane = tid & 31;
    int sblk = blockIdx.x * 256;

    // v[b] reduced from 8 split-K partials into smem
    {
        const int BE4 = MAX_B * MAX_E / 4;
        const float4* vp = reinterpret_cast<const float4*>(&g_part2[0]) + b * 128;
        if (tid < 128) {
            float4 r = vp[tid];
#pragma unroll
            for (int p = 1; p < SPLITK; p++) {
                float4 pp = vp[p * BE4 + tid];
                r.x += pp.x; r.y += pp.y; r.z += pp.z; r.w += pp.w;
            }
            vsh[tid] = r;
        }
    }

    const int* mrow = mask + (size_t)b * S;
    float* erow = out + (size_t)b * S;
    const float4* tb = reinterpret_cast<const float4*>(target) +
                       ((size_t)b * S + sblk) * 128;

    // compact kept rows (thread tid owns row tid of this block)
    bool keep = (mrow[sblk + tid] != 1);
    if (!keep) erow[sblk + tid] = 0.0f;
    unsigned bits = __ballot_sync(0xffffffffu, keep);
    if (lane == 0) s_wcnt[warp] = __popc(bits);
    __syncthreads();
    if (tid == 0) {
        int a = 0;
#pragma unroll
        for (int w = 0; w < 8; w++) { s_wbase[w] = a; a += s_wcnt[w]; }
        s_wbase[8] = a;
    }
    __syncthreads();
    if (keep)
        s_list[s_wbase[warp] + __popc(bits & ((1u << lane) - 1))] = (unsigned char)tid;
    __syncthreads();
    int nk = s_wbase[8];

    float cb = g_c[b];
    float esum = 0.0f;

#define LOADROW(buf, r) { const float4* t_ = tb + (size_t)(r) * 128;            \
        buf[0] = __ldcs(t_ + lane);       buf[1] = __ldcs(t_ + lane + 32);      \
        buf[2] = __ldcs(t_ + lane + 64);  buf[3] = __ldcs(t_ + lane + 96); }

#define DOTV(buf, a) { a = 0.0f;                                                \
        _Pragma("unroll") for (int j_ = 0; j_ < 4; j_++) {                      \
            float4 x_ = buf[j_]; float4 v_ = vsh[lane + 32 * j_];               \
            a += x_.x * v_.x + x_.y * v_.y + x_.z * v_.z + x_.w * v_.w; } }

#define REDUCE_EMIT(a, r) {                                                     \
        _Pragma("unroll") for (int o_ = 16; o_; o_ >>= 1)                       \
            a += __shfl_xor_sync(0xffffffffu, a, o_);                           \
        if (lane == 0) {                                                        \
            float e_ = expf(10.0f * tanhf(a + cb) - 10.0f);                     \
            erow[sblk + (r)] = e_; esum += e_; } }

    {
        float4 bufA[4], bufB[4];
        int rA = (warp < nk) ? (int)s_list[warp] : -1;
        int rB = (warp + 8 < nk) ? (int)s_list[warp + 8] : -1;
        if (rA >= 0) LOADROW(bufA, rA);
        if (rB >= 0) LOADROW(bufB, rB);
        int pn = warp + 16;
        while (rA >= 0) {
            float a;
            DOTV(bufA, a);
            int rn = (pn < nk) ? (int)s_list[pn] : -1; pn += 8;
            if (rn >= 0) LOADROW(bufA, rn);
            REDUCE_EMIT(a, rA);
            rA = rn;
            if (rB < 0) break;
            rn = (pn < nk) ? (int)s_list[pn] : -1; pn += 8;
            DOTV(bufB, a);
            if (rn >= 0) LOADROW(bufB, rn);
            REDUCE_EMIT(a, rB);
            rB = rn;
        }
    }

    if (lane == 0 && esum != 0.0f)
        atomicAdd(&g_sum[b], esum);

    __threadfence();
    __syncthreads();
    if (tid == 0) {
        unsigned t = atomicAdd(&g_cnt[b], 1u);
        lastdone = (t == gridDim.x - 1);
    }
    __syncthreads();

    if (lastdone) {
        __threadfence();
        float inv = 1.0f / g_sum[b];
        float4* rowv = reinterpret_cast<float4*>(out + (size_t)b * S);
        for (int i = tid; i < S / 4; i += 256) {
            float4 x = rowv[i];
            x.x *= inv; x.y *= inv; x.z *= inv; x.w *= inv;
            rowv[i] = x;
        }
    }
}

// ---------------------------------------------------------------------------
// Inputs (metadata order): query[B,E], target[B,S,E], mask[B,S],
//                          Wq[H,E], bq[H], Wk[H,E], bk[H]
// Output: alpha[B,S] float32
// ---------------------------------------------------------------------------
extern "C" void kernel_launch(void* const* d_in, const int* in_sizes, int n_in,
                              void* d_out, int out_size)
{
    const float* query  = (const float*)d_in[0];
    const float* target = (const float*)d_in[1];
    const int*   mask   = (const int*)d_in[2];
    const float* Wq     = (const float*)d_in[3];
    const float* bq     = (const float*)d_in[4];
    const float* Wk     = (const float*)d_in[5];
    const float* bk     = (const float*)d_in[6];
    float* out = (float*)d_out;

    int H = in_sizes[4];
    int E = in_sizes[1] / in_sizes[2];
    int B = in_sizes[0] / E;
    int S = in_sizes[2] / B;

    float* part_ptr; float* part2_ptr;
    cudaGetSymbolAddress((void**)&part_ptr, g_part);
    cudaGetSymbolAddress((void**)&part2_ptr, g_part2);

    // q partials: query @ Wq^T -> g_part  (also zeroes g_c/g_sum/g_cnt)
    {
        dim3 grid(H / 64, B / 64, SPLITK);
        gemm_split_kernel<1, 0><<<grid, 256>>>(query, nullptr, Wq, nullptr,
                                               part_ptr, B, H, E);
    }
    // v partials: (q summed + bq) @ Wk -> g_part2 ; also accumulates c[b]
    {
        dim3 grid(E / 64, B / 64, SPLITK);
        gemm_split_kernel<0, 1><<<grid, 256>>>(part_ptr, bq, Wk, bk,
                                               part2_ptr, B, E, H);
    }
    // fused score + softmax (mask-skip, balanced, last-block normalize)
    {
        dim3 grid(S / 256, B);
        score_kernel<<<grid, 256>>>(target, mask, out, S);
    }
}